// round 15
// baseline (speedup 1.0000x reference)
#include <cuda_runtime.h>
#include <math.h>

#define D_MODEL 1024
#define NHEAD 16
#define HEAD_DIM 64
#define B_ 2
#define T_ 2048
#define M_TOT (B_ * T_)   // 4096

// Scratch (allocation-free: __device__ globals)
__device__ float g_Q[M_TOT * D_MODEL];
__device__ float g_K[M_TOT * D_MODEL];
__device__ float g_V[M_TOT * D_MODEL];
__device__ float g_O[M_TOT * D_MODEL];

// ---------------------------------------------------------------------------
// tf32 helpers
// ---------------------------------------------------------------------------
__device__ __forceinline__ float to_tf32(float x) {
    unsigned u;
    asm("cvt.rna.tf32.f32 %0, %1;" : "=r"(u) : "f"(x));
    return __uint_as_float(u);
}

// D += A(16x8) * B(8x8), tf32, row.col
__device__ __forceinline__ void mma_tf32(float* c, const float* a, const float* b) {
    asm("mma.sync.aligned.m16n8k8.row.col.f32.tf32.tf32.f32 "
        "{%0,%1,%2,%3}, {%4,%5,%6,%7}, {%8,%9}, {%0,%1,%2,%3};"
        : "+f"(c[0]), "+f"(c[1]), "+f"(c[2]), "+f"(c[3])
        : "r"(__float_as_uint(a[0])), "r"(__float_as_uint(a[1])),
          "r"(__float_as_uint(a[2])), "r"(__float_as_uint(a[3])),
          "r"(__float_as_uint(b[0])), "r"(__float_as_uint(b[1])));
}

// ---------------------------------------------------------------------------
// tf32 tensor-core GEMM: C[M,N] = A[M,K] @ W[K,N] + bias[N]
// BM=128, BN=128, BK=32, 256 threads = 8 warps (4 M x 2 N), warp tile 32x64.
// Operands staged into fragment-layout smem (conflict-free LDS.128/LDS.64).
// ---------------------------------------------------------------------------
__global__ __launch_bounds__(256) void gemm_tf32_kernel(
    const float* __restrict__ A, const float* __restrict__ W,
    const float* __restrict__ bias, float* __restrict__ C,
    int M, int N, int K)
{
    // Af[mt(8)][ks(4)][lane(32)][slot(4)]  = 4096 floats
    // Bf[nt(16)][ks(4)][lane(32)][slot(2)] = 4096 floats
    __shared__ float Af[4096];
    __shared__ float Bf[4096];

    const int t = threadIdx.x;
    const int warp = t >> 5, lane = t & 31;
    const int g = lane >> 2, tig = lane & 3;
    const int wm = warp >> 1, wn = warp & 1;
    const int bm = blockIdx.y * 128;
    const int bn = blockIdx.x * 128;

    float acc[2][8][4];
#pragma unroll
    for (int i = 0; i < 2; i++)
#pragma unroll
        for (int j = 0; j < 8; j++)
#pragma unroll
            for (int l = 0; l < 4; l++) acc[i][j][l] = 0.f;

    for (int k0 = 0; k0 < K; k0 += 32) {
        __syncthreads();
        // stage A (128x32) into fragment layout
#pragma unroll
        for (int i = 0; i < 4; i++) {
            int f4 = t + i * 256;               // 0..1023
            int ml = f4 >> 3, kl = (f4 & 7) * 4;
            float4 v = *(const float4*)&A[(size_t)(bm + ml) * K + k0 + kl];
            int mt = ml >> 4, ga = ml & 7, sm = (ml >> 3) & 1;
            int ks = kl >> 3, sk = (kl >> 2) & 1;
            int slot = sm + 2 * sk;
            int base = ((mt * 4 + ks) * 32 + ga * 4) * 4 + slot;
            Af[base + 0 * 4] = to_tf32(v.x);
            Af[base + 1 * 4] = to_tf32(v.y);
            Af[base + 2 * 4] = to_tf32(v.z);
            Af[base + 3 * 4] = to_tf32(v.w);
        }
        // stage W (32x128) into fragment layout
#pragma unroll
        for (int i = 0; i < 4; i++) {
            int f4 = t + i * 256;
            int kl = f4 >> 5, nl = (f4 & 31) * 4;
            float4 v = *(const float4*)&W[(size_t)(k0 + kl) * N + bn + nl];
            int ks = kl >> 3, tg = kl & 3, slot = (kl >> 2) & 1;
            float vv[4] = {v.x, v.y, v.z, v.w};
#pragma unroll
            for (int j = 0; j < 4; j++) {
                int n = nl + j;
                int nt = n >> 3, gb = n & 7;
                Bf[((nt * 4 + ks) * 32 + gb * 4 + tg) * 2 + slot] = to_tf32(vv[j]);
            }
        }
        __syncthreads();

#pragma unroll
        for (int ks = 0; ks < 4; ks++) {
            float a[2][4];
#pragma unroll
            for (int lm = 0; lm < 2; lm++) {
                int mt = wm * 2 + lm;
                *(float4*)a[lm] = *(const float4*)&Af[((mt * 4 + ks) * 32 + lane) * 4];
            }
#pragma unroll
            for (int ln = 0; ln < 8; ln++) {
                int nt = wn * 8 + ln;
                float b[2];
                *(float2*)b = *(const float2*)&Bf[((nt * 4 + ks) * 32 + lane) * 2];
                mma_tf32(acc[0][ln], a[0], b);
                mma_tf32(acc[1][ln], a[1], b);
            }
        }
    }

    // epilogue: bias + store (STG.64)
#pragma unroll
    for (int lm = 0; lm < 2; lm++) {
        int m0 = bm + wm * 32 + lm * 16 + g;
#pragma unroll
        for (int ln = 0; ln < 8; ln++) {
            int n0 = bn + wn * 64 + ln * 8 + 2 * tig;
            float2 bi = *(const float2*)&bias[n0];
            float2 o0, o1;
            o0.x = acc[lm][ln][0] + bi.x;
            o0.y = acc[lm][ln][1] + bi.y;
            o1.x = acc[lm][ln][2] + bi.x;
            o1.y = acc[lm][ln][3] + bi.y;
            *(float2*)&C[(size_t)m0 * N + n0] = o0;
            *(float2*)&C[(size_t)(m0 + 8) * N + n0] = o1;
        }
    }
}

// ---------------------------------------------------------------------------
// RoPE in-place on Q and K; Q also gets the 1/sqrt(hd) score scale folded in.
// ---------------------------------------------------------------------------
__global__ void rope_kernel(float* __restrict__ Q, float* __restrict__ K)
{
    int idx = blockIdx.x * blockDim.x + threadIdx.x;
    const int TOTAL = B_ * T_ * NHEAD * 32;
    if (idx >= TOTAL) return;
    int i = idx & 31;
    int h = (idx >> 5) & (NHEAD - 1);
    int t = (idx >> 9) & (T_ - 1);
    int b = idx >> 20;

    float freq = (float)t / powf(10000.0f, (float)i / 32.0f);
    float s, c;
    sincosf(freq, &s, &c);

    int base = ((b * T_ + t) * D_MODEL) + h * HEAD_DIM;
    const float scale = 0.125f;  // 64^-0.5

    float ql = Q[base + i], qr = Q[base + i + 32];
    Q[base + i]      = (ql * c - qr * s) * scale;
    Q[base + i + 32] = (ql * s + qr * c) * scale;

    float kl = K[base + i], kr = K[base + i + 32];
    K[base + i]      = kl * c - kr * s;
    K[base + i + 32] = kl * s + kr * c;
}

// ---------------------------------------------------------------------------
// Flash attention, tf32 mma. 64-query tile / block, 128 threads = 4 warps.
// Warp w owns query rows [16w, 16w+16) and the full 64-key tile: online
// softmax stays warp-local (accumulator rows g, g+8 are architectural).
// Smem (floats):
//   Qf[mt(4)][ks(8)][lane][4]  = 4096  (A fragments, loaded once)
//   Kf[nt(8)][ks(8)][lane][2]  = 4096  (B fragments, per key tile)
//   Vf[nt(8)][kv(8)][lane][2]  = 4096  (B fragments, per key tile)
//   Ps: 4 warps x 16 x 68      = 4352  (P round-trip, stride 68 = no conflicts)
//   fk[64]
// ---------------------------------------------------------------------------
#define AT_SMEM_FLOATS (4096*3 + 4*16*68 + 64)
#define AT_SMEM_BYTES (AT_SMEM_FLOATS * 4)

__global__ __launch_bounds__(128) void attn_mma_kernel(
    const float* __restrict__ Q, const float* __restrict__ K,
    const float* __restrict__ V, float* __restrict__ O,
    const float* __restrict__ frac,
    const float* __restrict__ alpha_pos, const float* __restrict__ alpha_neg)
{
    extern __shared__ float sm[];
    float* Qf = sm;
    float* Kf = Qf + 4096;
    float* Vf = Kf + 4096;
    float* Ps = Vf + 4096;
    float* fk = Ps + 4 * 16 * 68;

    const int t = threadIdx.x;
    const int w = t >> 5, lane = t & 31;
    const int g = lane >> 2, tig = lane & 3;
    const int qt = blockIdx.x, h = blockIdx.y, b = blockIdx.z;
    const int t0 = qt * 64;
    const int bT = b * T_;

    const float ap = alpha_pos[h];
    const float an = alpha_neg[h];

    float* Pw = Ps + w * 16 * 68;

    // stage Q tile (64x64) into A-fragment layout
#pragma unroll
    for (int i = 0; i < 8; i++) {
        int f4 = t + i * 128;               // 0..1023
        int ql = f4 >> 4, dl = (f4 & 15) * 4;
        float4 v = *(const float4*)&Q[(size_t)(bT + t0 + ql) * D_MODEL + h * HEAD_DIM + dl];
        int mt = ql >> 4, ga = ql & 7, smb = (ql >> 3) & 1;
        int ks = dl >> 3, sk = (dl >> 2) & 1;
        int slot = smb + 2 * sk;
        int base = ((mt * 8 + ks) * 32 + ga * 4) * 4 + slot;
        Qf[base + 0 * 4] = to_tf32(v.x);
        Qf[base + 1 * 4] = to_tf32(v.y);
        Qf[base + 2 * 4] = to_tf32(v.z);
        Qf[base + 3 * 4] = to_tf32(v.w);
    }

    const float fq_g  = frac[bT + t0 + w * 16 + g];
    const float fq_g8 = frac[bT + t0 + w * 16 + g + 8];

    float m_g = -1e30f, m_g8 = -1e30f, l_g = 0.f, l_g8 = 0.f;
    float oacc[8][4];
#pragma unroll
    for (int i = 0; i < 8; i++)
#pragma unroll
        for (int j = 0; j < 4; j++) oacc[i][j] = 0.f;

    for (int kt = 0; kt < T_ / 64; kt++) {
        int tk0 = kt * 64;
        __syncthreads();   // prev PV done (and Qf ready on first iter)

        // stage K tile -> B fragments (S = Q @ K^T: B row=d, col=key)
#pragma unroll
        for (int i = 0; i < 8; i++) {
            int f4 = t + i * 128;
            int kl = f4 >> 4, dl = (f4 & 15) * 4;
            float4 v = *(const float4*)&K[(size_t)(bT + tk0 + kl) * D_MODEL + h * HEAD_DIM + dl];
            int nt = kl >> 3, gb = kl & 7;
            int ks = dl >> 3, sk = (dl >> 2) & 1;
            int base = ((nt * 8 + ks) * 32 + gb * 4) * 2 + sk;
            Kf[base + 0 * 2] = to_tf32(v.x);
            Kf[base + 1 * 2] = to_tf32(v.y);
            Kf[base + 2 * 2] = to_tf32(v.z);
            Kf[base + 3 * 2] = to_tf32(v.w);
        }
        // stage V tile -> B fragments (O = P @ V: B row=key, col=d)
#pragma unroll
        for (int i = 0; i < 8; i++) {
            int f4 = t + i * 128;
            int kl = f4 >> 4, dl = (f4 & 15) * 4;
            float4 v = *(const float4*)&V[(size_t)(bT + tk0 + kl) * D_MODEL + h * HEAD_DIM + dl];
            int kv = kl >> 3, tg = kl & 3, slot = (kl >> 2) & 1;
            int ntd = dl >> 3;
            int g0 = dl & 7;
            float vv[4] = {v.x, v.y, v.z, v.w};
#pragma unroll
            for (int j = 0; j < 4; j++)
                Vf[((ntd * 8 + kv) * 32 + (g0 + j) * 4 + tg) * 2 + slot] = to_tf32(vv[j]);
        }
        if (t < 64) fk[t] = frac[bT + tk0 + t];
        __syncthreads();

        // ---- S = Q @ K^T (16q x 64k per warp) ----
        float sacc[8][4];
#pragma unroll
        for (int i = 0; i < 8; i++)
#pragma unroll
            for (int j = 0; j < 4; j++) sacc[i][j] = 0.f;

#pragma unroll
        for (int ks = 0; ks < 8; ks++) {
            float a[4];
            *(float4*)a = *(const float4*)&Qf[((w * 8 + ks) * 32 + lane) * 4];
#pragma unroll
            for (int nt = 0; nt < 8; nt++) {
                float bb[2];
                *(float2*)bb = *(const float2*)&Kf[((nt * 8 + ks) * 32 + lane) * 2];
                mma_tf32(sacc[nt], a, bb);
            }
        }

        // ---- bias + online softmax (rows g, g+8; cols nt*8 + 2tig{,+1}) ----
        float tmax_g = -1e30f, tmax_g8 = -1e30f;
#pragma unroll
        for (int nt = 0; nt < 8; nt++) {
            float2 f2 = *(const float2*)&fk[nt * 8 + 2 * tig];
            float d0 = f2.x - fq_g;   sacc[nt][0] += (d0 > 0.f ? ap : an) * d0;
            float d1 = f2.y - fq_g;   sacc[nt][1] += (d1 > 0.f ? ap : an) * d1;
            float d2 = f2.x - fq_g8;  sacc[nt][2] += (d2 > 0.f ? ap : an) * d2;
            float d3 = f2.y - fq_g8;  sacc[nt][3] += (d3 > 0.f ? ap : an) * d3;
            tmax_g  = fmaxf(tmax_g,  fmaxf(sacc[nt][0], sacc[nt][1]));
            tmax_g8 = fmaxf(tmax_g8, fmaxf(sacc[nt][2], sacc[nt][3]));
        }
        tmax_g  = fmaxf(tmax_g,  __shfl_xor_sync(0xffffffffu, tmax_g, 1));
        tmax_g  = fmaxf(tmax_g,  __shfl_xor_sync(0xffffffffu, tmax_g, 2));
        tmax_g8 = fmaxf(tmax_g8, __shfl_xor_sync(0xffffffffu, tmax_g8, 1));
        tmax_g8 = fmaxf(tmax_g8, __shfl_xor_sync(0xffffffffu, tmax_g8, 2));

        float mn_g  = fmaxf(m_g,  tmax_g);
        float mn_g8 = fmaxf(m_g8, tmax_g8);
        float corr_g  = __expf(m_g  - mn_g);
        float corr_g8 = __expf(m_g8 - mn_g8);

        float rs_g = 0.f, rs_g8 = 0.f;
#pragma unroll
        for (int nt = 0; nt < 8; nt++) {
            float p0 = __expf(sacc[nt][0] - mn_g);
            float p1 = __expf(sacc[nt][1] - mn_g);
            float p2 = __expf(sacc[nt][2] - mn_g8);
            float p3 = __expf(sacc[nt][3] - mn_g8);
            rs_g  += p0 + p1;
            rs_g8 += p2 + p3;
            float2 st0; st0.x = to_tf32(p0); st0.y = to_tf32(p1);
            float2 st1; st1.x = to_tf32(p2); st1.y = to_tf32(p3);
            *(float2*)&Pw[g * 68 + nt * 8 + 2 * tig]       = st0;
            *(float2*)&Pw[(g + 8) * 68 + nt * 8 + 2 * tig] = st1;
        }
        rs_g  += __shfl_xor_sync(0xffffffffu, rs_g, 1);
        rs_g  += __shfl_xor_sync(0xffffffffu, rs_g, 2);
        rs_g8 += __shfl_xor_sync(0xffffffffu, rs_g8, 1);
        rs_g8 += __shfl_xor_sync(0xffffffffu, rs_g8, 2);

        l_g  = l_g  * corr_g  + rs_g;
        l_g8 = l_g8 * corr_g8 + rs_g8;
        m_g = mn_g; m_g8 = mn_g8;

#pragma unroll
        for (int nt = 0; nt < 8; nt++) {
            oacc[nt][0] *= corr_g;  oacc[nt][1] *= corr_g;
            oacc[nt][2] *= corr_g8; oacc[nt][3] *= corr_g8;
        }
        __syncwarp();

        // ---- O += P @ V ----
#pragma unroll
        for (int kv = 0; kv < 8; kv++) {
            float a[4];
            a[0] = Pw[g * 68 + kv * 8 + tig];
            a[1] = Pw[(g + 8) * 68 + kv * 8 + tig];
            a[2] = Pw[g * 68 + kv * 8 + tig + 4];
            a[3] = Pw[(g + 8) * 68 + kv * 8 + tig + 4];
#pragma unroll
            for (int nt = 0; nt < 8; nt++) {
                float bb[2];
                *(float2*)bb = *(const float2*)&Vf[((nt * 8 + kv) * 32 + lane) * 2];
                mma_tf32(oacc[nt], a, bb);
            }
        }
    }

    // epilogue: normalize, store [B,T,D]
    float inv_g = 1.0f / l_g, inv_g8 = 1.0f / l_g8;
    int tq = t0 + w * 16 + g;
#pragma unroll
    for (int nt = 0; nt < 8; nt++) {
        int col = h * HEAD_DIM + nt * 8 + 2 * tig;
        float2 o0, o1;
        o0.x = oacc[nt][0] * inv_g;  o0.y = oacc[nt][1] * inv_g;
        o1.x = oacc[nt][2] * inv_g8; o1.y = oacc[nt][3] * inv_g8;
        *(float2*)&O[(size_t)(bT + tq) * D_MODEL + col] = o0;
        *(float2*)&O[(size_t)(bT + tq + 8) * D_MODEL + col] = o1;
    }
}

// ---------------------------------------------------------------------------
// Launch
// Inputs: 0 query, 1 key, 2 value, 3 frac, 4 Wq, 5 Wk, 6 Wv, 7 Wo,
//         8 bq, 9 bk, 10 bv, 11 bo, 12 alpha_pos, 13 alpha_neg
// ---------------------------------------------------------------------------
extern "C" void kernel_launch(void* const* d_in, const int* in_sizes, int n_in,
                              void* d_out, int out_size)
{
    const float* query = (const float*)d_in[0];
    const float* key   = (const float*)d_in[1];
    const float* value = (const float*)d_in[2];
    const float* frac  = (const float*)d_in[3];
    const float* Wq    = (const float*)d_in[4];
    const float* Wk    = (const float*)d_in[5];
    const float* Wv    = (const float*)d_in[6];
    const float* Wo    = (const float*)d_in[7];
    const float* bq    = (const float*)d_in[8];
    const float* bk    = (const float*)d_in[9];
    const float* bv    = (const float*)d_in[10];
    const float* bo    = (const float*)d_in[11];
    const float* a_pos = (const float*)d_in[12];
    const float* a_neg = (const float*)d_in[13];
    float* out = (float*)d_out;

    float *pQ, *pK, *pV, *pO;
    cudaGetSymbolAddress((void**)&pQ, g_Q);
    cudaGetSymbolAddress((void**)&pK, g_K);
    cudaGetSymbolAddress((void**)&pV, g_V);
    cudaGetSymbolAddress((void**)&pO, g_O);

    dim3 gemm_grid(D_MODEL / 128, M_TOT / 128);

    gemm_tf32_kernel<<<gemm_grid, 256>>>(query, Wq, bq, pQ, M_TOT, D_MODEL, D_MODEL);
    gemm_tf32_kernel<<<gemm_grid, 256>>>(key,   Wk, bk, pK, M_TOT, D_MODEL, D_MODEL);
    gemm_tf32_kernel<<<gemm_grid, 256>>>(value, Wv, bv, pV, M_TOT, D_MODEL, D_MODEL);

    int rope_threads = B_ * T_ * NHEAD * 32;
    rope_kernel<<<(rope_threads + 255) / 256, 256>>>(pQ, pK);

    cudaFuncSetAttribute(attn_mma_kernel, cudaFuncAttributeMaxDynamicSharedMemorySize, AT_SMEM_BYTES);
    attn_mma_kernel<<<dim3(T_ / 64, NHEAD, B_), 128, AT_SMEM_BYTES>>>(
        pQ, pK, pV, pO, frac, a_pos, a_neg);

    gemm_tf32_kernel<<<gemm_grid, 256>>>(pO, Wo, bo, out, M_TOT, D_MODEL, D_MODEL);
}

// round 16
// speedup vs baseline: 1.0778x; 1.0778x over previous
#include <cuda_runtime.h>
#include <math.h>

#define D_MODEL 1024
#define NHEAD 16
#define HEAD_DIM 64
#define B_ 2
#define T_ 2048
#define M_TOT (B_ * T_)   // 4096

// Scratch (allocation-free: __device__ globals)
__device__ float g_Q[M_TOT * D_MODEL];
__device__ float g_K[M_TOT * D_MODEL];
__device__ float g_V[M_TOT * D_MODEL];
__device__ float g_O[M_TOT * D_MODEL];

// ---------------------------------------------------------------------------
// tf32 helpers
// ---------------------------------------------------------------------------
__device__ __forceinline__ float to_tf32(float x) {
    unsigned u;
    asm("cvt.rna.tf32.f32 %0, %1;" : "=r"(u) : "f"(x));
    return __uint_as_float(u);
}

// D += A(16x8) * B(8x8), tf32, row.col
__device__ __forceinline__ void mma_tf32(float* c, const float* a, const float* b) {
    asm("mma.sync.aligned.m16n8k8.row.col.f32.tf32.tf32.f32 "
        "{%0,%1,%2,%3}, {%4,%5,%6,%7}, {%8,%9}, {%0,%1,%2,%3};"
        : "+f"(c[0]), "+f"(c[1]), "+f"(c[2]), "+f"(c[3])
        : "r"(__float_as_uint(a[0])), "r"(__float_as_uint(a[1])),
          "r"(__float_as_uint(a[2])), "r"(__float_as_uint(a[3])),
          "r"(__float_as_uint(b[0])), "r"(__float_as_uint(b[1])));
}

// ---------------------------------------------------------------------------
// tf32 tensor-core GEMM with z-indexed operand sets (fused QKV) and
// register-prefetch software pipeline.
// C[M,N] = A[M,K] @ W[K,N] + bias[N]
// BM=128, BN=128, BK=32, 256 threads = 8 warps (4 M x 2 N), warp tile 32x64.
// ---------------------------------------------------------------------------
struct GemmArgs {
    const float* A[3];
    const float* W[3];
    const float* bias[3];
    float* C[3];
};

__global__ __launch_bounds__(256) void gemm_tf32_kernel(
    GemmArgs args, int M, int N, int K)
{
    const int z = blockIdx.z;
    const float* __restrict__ A    = args.A[z];
    const float* __restrict__ W    = args.W[z];
    const float* __restrict__ bias = args.bias[z];
    float* __restrict__ C          = args.C[z];

    // Af[mt(8)][ks(4)][lane(32)][slot(4)]  = 4096 floats
    // Bf[nt(16)][ks(4)][lane(32)][slot(2)] = 4096 floats
    __shared__ float Af[4096];
    __shared__ float Bf[4096];

    const int t = threadIdx.x;
    const int warp = t >> 5, lane = t & 31;
    const int g = lane >> 2, tig = lane & 3;
    const int wm = warp >> 1, wn = warp & 1;
    const int bm = blockIdx.y * 128;
    const int bn = blockIdx.x * 128;

    // per-thread staging coordinates
    const int a_ml0 = t >> 3;                 // for i-th chunk: ml = a_ml0 + ... (see loop)
    const int a_kl0 = (t & 7) * 4;
    const int w_kl0 = t >> 5;
    const int w_nl0 = (t & 31) * 4;

    float acc[2][8][4];
#pragma unroll
    for (int i = 0; i < 2; i++)
#pragma unroll
        for (int j = 0; j < 8; j++)
#pragma unroll
            for (int l = 0; l < 4; l++) acc[i][j][l] = 0.f;

    float4 pa[4], pw[4];
    // prefetch k0 = 0
#pragma unroll
    for (int i = 0; i < 4; i++) {
        int f4 = t + i * 256;
        int ml = f4 >> 3, kl = (f4 & 7) * 4;
        pa[i] = *(const float4*)&A[(size_t)(bm + ml) * K + kl];
        int kl2 = f4 >> 5, nl = (f4 & 31) * 4;
        pw[i] = *(const float4*)&W[(size_t)kl2 * N + bn + nl];
    }

    for (int k0 = 0; k0 < K; k0 += 32) {
        __syncthreads();   // consumers of previous tile done
        // stage A from prefetch regs
#pragma unroll
        for (int i = 0; i < 4; i++) {
            int f4 = t + i * 256;
            int ml = f4 >> 3, kl = (f4 & 7) * 4;
            int mt = ml >> 4, ga = ml & 7, sm = (ml >> 3) & 1;
            int ks = kl >> 3, sk = (kl >> 2) & 1;
            int slot = sm + 2 * sk;
            int base = ((mt * 4 + ks) * 32 + ga * 4) * 4 + slot;
            Af[base + 0 * 4] = to_tf32(pa[i].x);
            Af[base + 1 * 4] = to_tf32(pa[i].y);
            Af[base + 2 * 4] = to_tf32(pa[i].z);
            Af[base + 3 * 4] = to_tf32(pa[i].w);
        }
        // stage W from prefetch regs
#pragma unroll
        for (int i = 0; i < 4; i++) {
            int f4 = t + i * 256;
            int kl = f4 >> 5, nl = (f4 & 31) * 4;
            int ks = kl >> 3, tg = kl & 3, slot = (kl >> 2) & 1;
            float vv[4] = {pw[i].x, pw[i].y, pw[i].z, pw[i].w};
#pragma unroll
            for (int j = 0; j < 4; j++) {
                int n = nl + j;
                int nt = n >> 3, gb = n & 7;
                Bf[((nt * 4 + ks) * 32 + gb * 4 + tg) * 2 + slot] = to_tf32(vv[j]);
            }
        }
        __syncthreads();

        // prefetch next tile (LDG overlaps the MMA mainloop below)
        if (k0 + 32 < K) {
            int kn = k0 + 32;
#pragma unroll
            for (int i = 0; i < 4; i++) {
                int f4 = t + i * 256;
                int ml = f4 >> 3, kl = (f4 & 7) * 4;
                pa[i] = *(const float4*)&A[(size_t)(bm + ml) * K + kn + kl];
                int kl2 = f4 >> 5, nl = (f4 & 31) * 4;
                pw[i] = *(const float4*)&W[(size_t)(kn + kl2) * N + bn + nl];
            }
        }

#pragma unroll
        for (int ks = 0; ks < 4; ks++) {
            float a[2][4];
#pragma unroll
            for (int lm = 0; lm < 2; lm++) {
                int mt = wm * 2 + lm;
                *(float4*)a[lm] = *(const float4*)&Af[((mt * 4 + ks) * 32 + lane) * 4];
            }
#pragma unroll
            for (int ln = 0; ln < 8; ln++) {
                int nt = wn * 8 + ln;
                float b[2];
                *(float2*)b = *(const float2*)&Bf[((nt * 4 + ks) * 32 + lane) * 2];
                mma_tf32(acc[0][ln], a[0], b);
                mma_tf32(acc[1][ln], a[1], b);
            }
        }
    }

    // epilogue: bias + store (STG.64)
#pragma unroll
    for (int lm = 0; lm < 2; lm++) {
        int m0 = bm + wm * 32 + lm * 16 + g;
#pragma unroll
        for (int ln = 0; ln < 8; ln++) {
            int n0 = bn + wn * 64 + ln * 8 + 2 * tig;
            float2 bi = *(const float2*)&bias[n0];
            float2 o0, o1;
            o0.x = acc[lm][ln][0] + bi.x;
            o0.y = acc[lm][ln][1] + bi.y;
            o1.x = acc[lm][ln][2] + bi.x;
            o1.y = acc[lm][ln][3] + bi.y;
            *(float2*)&C[(size_t)m0 * N + n0] = o0;
            *(float2*)&C[(size_t)(m0 + 8) * N + n0] = o1;
        }
    }
    (void)a_ml0; (void)a_kl0; (void)w_kl0; (void)w_nl0;
}

// ---------------------------------------------------------------------------
// RoPE in-place on Q and K; Q also gets the 1/sqrt(hd) score scale folded in.
// ---------------------------------------------------------------------------
__global__ void rope_kernel(float* __restrict__ Q, float* __restrict__ K)
{
    int idx = blockIdx.x * blockDim.x + threadIdx.x;
    const int TOTAL = B_ * T_ * NHEAD * 32;
    if (idx >= TOTAL) return;
    int i = idx & 31;
    int h = (idx >> 5) & (NHEAD - 1);
    int t = (idx >> 9) & (T_ - 1);
    int b = idx >> 20;

    float freq = (float)t / powf(10000.0f, (float)i / 32.0f);
    float s, c;
    sincosf(freq, &s, &c);

    int base = ((b * T_ + t) * D_MODEL) + h * HEAD_DIM;
    const float scale = 0.125f;  // 64^-0.5

    float ql = Q[base + i], qr = Q[base + i + 32];
    Q[base + i]      = (ql * c - qr * s) * scale;
    Q[base + i + 32] = (ql * s + qr * c) * scale;

    float kl = K[base + i], kr = K[base + i + 32];
    K[base + i]      = kl * c - kr * s;
    K[base + i + 32] = kl * s + kr * c;
}

// ---------------------------------------------------------------------------
// Flash attention, tf32 mma. 128-query tile / block, 256 threads = 8 warps.
// Warp w owns query rows [16w, 16w+16) and the full 64-key tile: online
// softmax stays warp-local. K/V tiles staged once per 128 queries (2x less
// gmem traffic than 64-query CTAs) and prefetched into registers while the
// previous tile's MMAs run.
// Smem (floats):
//   Qf[mt(8)][ks(8)][lane][4]  = 8192  (A fragments, loaded once)
//   Kf[nt(8)][ks(8)][lane][2]  = 4096  (B fragments, per key tile)
//   Vf[nt(8)][kv(8)][lane][2]  = 4096  (B fragments, per key tile)
//   Ps: 8 warps x 16 x 68      = 8704  (P round-trip, stride 68 = no conflicts)
//   fk[64]
// ---------------------------------------------------------------------------
#define AT_SMEM_FLOATS (8192 + 4096 + 4096 + 8*16*68 + 64)
#define AT_SMEM_BYTES (AT_SMEM_FLOATS * 4)

__global__ __launch_bounds__(256) void attn_mma_kernel(
    const float* __restrict__ Q, const float* __restrict__ K,
    const float* __restrict__ V, float* __restrict__ O,
    const float* __restrict__ frac,
    const float* __restrict__ alpha_pos, const float* __restrict__ alpha_neg)
{
    extern __shared__ float sm[];
    float* Qf = sm;
    float* Kf = Qf + 8192;
    float* Vf = Kf + 4096;
    float* Ps = Vf + 4096;
    float* fk = Ps + 8 * 16 * 68;

    const int t = threadIdx.x;
    const int w = t >> 5, lane = t & 31;
    const int g = lane >> 2, tig = lane & 3;
    const int qt = blockIdx.x, h = blockIdx.y, b = blockIdx.z;
    const int t0 = qt * 128;
    const int bT = b * T_;

    const float ap = alpha_pos[h];
    const float an = alpha_neg[h];

    float* Pw = Ps + w * 16 * 68;

    // stage Q tile (128x64) into A-fragment layout
#pragma unroll
    for (int i = 0; i < 8; i++) {
        int f4 = t + i * 256;               // 0..2047
        int ql = f4 >> 4, dl = (f4 & 15) * 4;
        float4 v = *(const float4*)&Q[(size_t)(bT + t0 + ql) * D_MODEL + h * HEAD_DIM + dl];
        int mt = ql >> 4, ga = ql & 7, smb = (ql >> 3) & 1;
        int ks = dl >> 3, sk = (dl >> 2) & 1;
        int slot = smb + 2 * sk;
        int base = ((mt * 8 + ks) * 32 + ga * 4) * 4 + slot;
        Qf[base + 0 * 4] = to_tf32(v.x);
        Qf[base + 1 * 4] = to_tf32(v.y);
        Qf[base + 2 * 4] = to_tf32(v.z);
        Qf[base + 3 * 4] = to_tf32(v.w);
    }

    const float fq_g  = frac[bT + t0 + w * 16 + g];
    const float fq_g8 = frac[bT + t0 + w * 16 + g + 8];

    float m_g = -1e30f, m_g8 = -1e30f, l_g = 0.f, l_g8 = 0.f;
    float oacc[8][4];
#pragma unroll
    for (int i = 0; i < 8; i++)
#pragma unroll
        for (int j = 0; j < 4; j++) oacc[i][j] = 0.f;

    // prefetch K/V tile 0
    float4 pk[4], pv[4];
#pragma unroll
    for (int i = 0; i < 4; i++) {
        int f4 = t + i * 256;               // 0..1023
        int kl = f4 >> 4, dl = (f4 & 15) * 4;
        size_t goff = (size_t)(bT + kl) * D_MODEL + h * HEAD_DIM + dl;
        pk[i] = *(const float4*)&K[goff];
        pv[i] = *(const float4*)&V[goff];
    }

    const int NT = T_ / 64;
    for (int kt = 0; kt < NT; kt++) {
        __syncthreads();   // prev tile's MMAs done (and Qf covered on iter 0)

        // stage K tile -> B fragments (S = Q @ K^T: B row=d, col=key)
#pragma unroll
        for (int i = 0; i < 4; i++) {
            int f4 = t + i * 256;
            int kl = f4 >> 4, dl = (f4 & 15) * 4;
            int nt = kl >> 3, gb = kl & 7;
            int ks = dl >> 3, sk = (dl >> 2) & 1;
            int base = ((nt * 8 + ks) * 32 + gb * 4) * 2 + sk;
            Kf[base + 0 * 2] = to_tf32(pk[i].x);
            Kf[base + 1 * 2] = to_tf32(pk[i].y);
            Kf[base + 2 * 2] = to_tf32(pk[i].z);
            Kf[base + 3 * 2] = to_tf32(pk[i].w);
        }
        // stage V tile -> B fragments (O = P @ V: B row=key, col=d)
#pragma unroll
        for (int i = 0; i < 4; i++) {
            int f4 = t + i * 256;
            int kl = f4 >> 4, dl = (f4 & 15) * 4;
            int kv = kl >> 3, tg = kl & 3, slot = (kl >> 2) & 1;
            int ntd = dl >> 3;
            int g0 = dl & 7;
            float vv[4] = {pv[i].x, pv[i].y, pv[i].z, pv[i].w};
#pragma unroll
            for (int j = 0; j < 4; j++)
                Vf[((ntd * 8 + kv) * 32 + (g0 + j) * 4 + tg) * 2 + slot] = to_tf32(vv[j]);
        }
        if (t < 64) fk[t] = frac[bT + kt * 64 + t];
        __syncthreads();

        // prefetch next K/V tile — LDG overlaps all MMA work below
        if (kt + 1 < NT) {
            int tk0n = (kt + 1) * 64;
#pragma unroll
            for (int i = 0; i < 4; i++) {
                int f4 = t + i * 256;
                int kl = f4 >> 4, dl = (f4 & 15) * 4;
                size_t goff = (size_t)(bT + tk0n + kl) * D_MODEL + h * HEAD_DIM + dl;
                pk[i] = *(const float4*)&K[goff];
                pv[i] = *(const float4*)&V[goff];
            }
        }

        // ---- S = Q @ K^T (16q x 64k per warp) ----
        float sacc[8][4];
#pragma unroll
        for (int i = 0; i < 8; i++)
#pragma unroll
            for (int j = 0; j < 4; j++) sacc[i][j] = 0.f;

#pragma unroll
        for (int ks = 0; ks < 8; ks++) {
            float a[4];
            *(float4*)a = *(const float4*)&Qf[((w * 8 + ks) * 32 + lane) * 4];
#pragma unroll
            for (int nt = 0; nt < 8; nt++) {
                float bb[2];
                *(float2*)bb = *(const float2*)&Kf[((nt * 8 + ks) * 32 + lane) * 2];
                mma_tf32(sacc[nt], a, bb);
            }
        }

        // ---- bias + online softmax (rows g, g+8; cols nt*8 + 2tig{,+1}) ----
        float tmax_g = -1e30f, tmax_g8 = -1e30f;
#pragma unroll
        for (int nt = 0; nt < 8; nt++) {
            float2 f2 = *(const float2*)&fk[nt * 8 + 2 * tig];
            float d0 = f2.x - fq_g;   sacc[nt][0] += (d0 > 0.f ? ap : an) * d0;
            float d1 = f2.y - fq_g;   sacc[nt][1] += (d1 > 0.f ? ap : an) * d1;
            float d2 = f2.x - fq_g8;  sacc[nt][2] += (d2 > 0.f ? ap : an) * d2;
            float d3 = f2.y - fq_g8;  sacc[nt][3] += (d3 > 0.f ? ap : an) * d3;
            tmax_g  = fmaxf(tmax_g,  fmaxf(sacc[nt][0], sacc[nt][1]));
            tmax_g8 = fmaxf(tmax_g8, fmaxf(sacc[nt][2], sacc[nt][3]));
        }
        tmax_g  = fmaxf(tmax_g,  __shfl_xor_sync(0xffffffffu, tmax_g, 1));
        tmax_g  = fmaxf(tmax_g,  __shfl_xor_sync(0xffffffffu, tmax_g, 2));
        tmax_g8 = fmaxf(tmax_g8, __shfl_xor_sync(0xffffffffu, tmax_g8, 1));
        tmax_g8 = fmaxf(tmax_g8, __shfl_xor_sync(0xffffffffu, tmax_g8, 2));

        float mn_g  = fmaxf(m_g,  tmax_g);
        float mn_g8 = fmaxf(m_g8, tmax_g8);
        float corr_g  = __expf(m_g  - mn_g);
        float corr_g8 = __expf(m_g8 - mn_g8);

        float rs_g = 0.f, rs_g8 = 0.f;
#pragma unroll
        for (int nt = 0; nt < 8; nt++) {
            float p0 = __expf(sacc[nt][0] - mn_g);
            float p1 = __expf(sacc[nt][1] - mn_g);
            float p2 = __expf(sacc[nt][2] - mn_g8);
            float p3 = __expf(sacc[nt][3] - mn_g8);
            rs_g  += p0 + p1;
            rs_g8 += p2 + p3;
            float2 st0; st0.x = to_tf32(p0); st0.y = to_tf32(p1);
            float2 st1; st1.x = to_tf32(p2); st1.y = to_tf32(p3);
            *(float2*)&Pw[g * 68 + nt * 8 + 2 * tig]       = st0;
            *(float2*)&Pw[(g + 8) * 68 + nt * 8 + 2 * tig] = st1;
        }
        rs_g  += __shfl_xor_sync(0xffffffffu, rs_g, 1);
        rs_g  += __shfl_xor_sync(0xffffffffu, rs_g, 2);
        rs_g8 += __shfl_xor_sync(0xffffffffu, rs_g8, 1);
        rs_g8 += __shfl_xor_sync(0xffffffffu, rs_g8, 2);

        l_g  = l_g  * corr_g  + rs_g;
        l_g8 = l_g8 * corr_g8 + rs_g8;
        m_g = mn_g; m_g8 = mn_g8;

#pragma unroll
        for (int nt = 0; nt < 8; nt++) {
            oacc[nt][0] *= corr_g;  oacc[nt][1] *= corr_g;
            oacc[nt][2] *= corr_g8; oacc[nt][3] *= corr_g8;
        }
        __syncwarp();

        // ---- O += P @ V ----
#pragma unroll
        for (int kv = 0; kv < 8; kv++) {
            float a[4];
            a[0] = Pw[g * 68 + kv * 8 + tig];
            a[1] = Pw[(g + 8) * 68 + kv * 8 + tig];
            a[2] = Pw[g * 68 + kv * 8 + tig + 4];
            a[3] = Pw[(g + 8) * 68 + kv * 8 + tig + 4];
#pragma unroll
            for (int nt = 0; nt < 8; nt++) {
                float bb[2];
                *(float2*)bb = *(const float2*)&Vf[((nt * 8 + kv) * 32 + lane) * 2];
                mma_tf32(oacc[nt], a, bb);
            }
        }
    }

    // epilogue: normalize, store [B,T,D]
    float inv_g = 1.0f / l_g, inv_g8 = 1.0f / l_g8;
    int tq = t0 + w * 16 + g;
#pragma unroll
    for (int nt = 0; nt < 8; nt++) {
        int col = h * HEAD_DIM + nt * 8 + 2 * tig;
        float2 o0, o1;
        o0.x = oacc[nt][0] * inv_g;  o0.y = oacc[nt][1] * inv_g;
        o1.x = oacc[nt][2] * inv_g8; o1.y = oacc[nt][3] * inv_g8;
        *(float2*)&O[(size_t)(bT + tq) * D_MODEL + col] = o0;
        *(float2*)&O[(size_t)(bT + tq + 8) * D_MODEL + col] = o1;
    }
}

// ---------------------------------------------------------------------------
// Launch
// Inputs: 0 query, 1 key, 2 value, 3 frac, 4 Wq, 5 Wk, 6 Wv, 7 Wo,
//         8 bq, 9 bk, 10 bv, 11 bo, 12 alpha_pos, 13 alpha_neg
// ---------------------------------------------------------------------------
extern "C" void kernel_launch(void* const* d_in, const int* in_sizes, int n_in,
                              void* d_out, int out_size)
{
    const float* query = (const float*)d_in[0];
    const float* key   = (const float*)d_in[1];
    const float* value = (const float*)d_in[2];
    const float* frac  = (const float*)d_in[3];
    const float* Wq    = (const float*)d_in[4];
    const float* Wk    = (const float*)d_in[5];
    const float* Wv    = (const float*)d_in[6];
    const float* Wo    = (const float*)d_in[7];
    const float* bq    = (const float*)d_in[8];
    const float* bk    = (const float*)d_in[9];
    const float* bv    = (const float*)d_in[10];
    const float* bo    = (const float*)d_in[11];
    const float* a_pos = (const float*)d_in[12];
    const float* a_neg = (const float*)d_in[13];
    float* out = (float*)d_out;

    float *pQ, *pK, *pV, *pO;
    cudaGetSymbolAddress((void**)&pQ, g_Q);
    cudaGetSymbolAddress((void**)&pK, g_K);
    cudaGetSymbolAddress((void**)&pV, g_V);
    cudaGetSymbolAddress((void**)&pO, g_O);

    // fused QKV projections (z-indexed)
    GemmArgs qkv;
    qkv.A[0] = query; qkv.A[1] = key; qkv.A[2] = value;
    qkv.W[0] = Wq;    qkv.W[1] = Wk;  qkv.W[2] = Wv;
    qkv.bias[0] = bq; qkv.bias[1] = bk; qkv.bias[2] = bv;
    qkv.C[0] = pQ;    qkv.C[1] = pK;  qkv.C[2] = pV;

    dim3 qkv_grid(D_MODEL / 128, M_TOT / 128, 3);
    gemm_tf32_kernel<<<qkv_grid, 256>>>(qkv, M_TOT, D_MODEL, D_MODEL);

    int rope_threads = B_ * T_ * NHEAD * 32;
    rope_kernel<<<(rope_threads + 255) / 256, 256>>>(pQ, pK);

    cudaFuncSetAttribute(attn_mma_kernel, cudaFuncAttributeMaxDynamicSharedMemorySize, AT_SMEM_BYTES);
    attn_mma_kernel<<<dim3(T_ / 128, NHEAD, B_), 256, AT_SMEM_BYTES>>>(
        pQ, pK, pV, pO, frac, a_pos, a_neg);

    // output projection (single operand set, grid z = 1)
    GemmArgs og;
    og.A[0] = pO; og.A[1] = pO; og.A[2] = pO;
    og.W[0] = Wo; og.W[1] = Wo; og.W[2] = Wo;
    og.bias[0] = bo; og.bias[1] = bo; og.bias[2] = bo;
    og.C[0] = out; og.C[1] = out; og.C[2] = out;

    dim3 o_grid(D_MODEL / 128, M_TOT / 128, 1);
    gemm_tf32_kernel<<<o_grid, 256>>>(og, M_TOT, D_MODEL, D_MODEL);
}

// round 17
// speedup vs baseline: 2.2071x; 2.0478x over previous
#include <cuda_runtime.h>
#include <math.h>

#define D_MODEL 1024
#define NHEAD 16
#define HEAD_DIM 64
#define B_ 2
#define T_ 2048
#define M_TOT (B_ * T_)   // 4096

// Scratch (allocation-free: __device__ globals)
__device__ float g_Q[M_TOT * D_MODEL];
__device__ float g_K[M_TOT * D_MODEL];
__device__ float g_V[M_TOT * D_MODEL];
__device__ float g_O[M_TOT * D_MODEL];

// ---------------------------------------------------------------------------
// tf32 helpers
// ---------------------------------------------------------------------------
__device__ __forceinline__ float to_tf32(float x) {
    unsigned u;
    asm("cvt.rna.tf32.f32 %0, %1;" : "=r"(u) : "f"(x));
    return __uint_as_float(u);
}

// D += A(16x8) * B(8x8), tf32, row.col
__device__ __forceinline__ void mma_tf32(float* c, const float* a, const float* b) {
    asm("mma.sync.aligned.m16n8k8.row.col.f32.tf32.tf32.f32 "
        "{%0,%1,%2,%3}, {%4,%5,%6,%7}, {%8,%9}, {%0,%1,%2,%3};"
        : "+f"(c[0]), "+f"(c[1]), "+f"(c[2]), "+f"(c[3])
        : "r"(__float_as_uint(a[0])), "r"(__float_as_uint(a[1])),
          "r"(__float_as_uint(a[2])), "r"(__float_as_uint(a[3])),
          "r"(__float_as_uint(b[0])), "r"(__float_as_uint(b[1])));
}

// ---------------------------------------------------------------------------
// tf32 tensor-core GEMM with z-indexed operand sets (fused QKV),
// register-prefetch pipeline, and XOR-swizzled fragment staging
// (kills the 8-32 way bank conflicts on the staging STS).
// C[M,N] = A[M,K] @ W[K,N] + bias[N]
// BM=128, BN=128, BK=32, 256 threads = 8 warps (4 M x 2 N), warp tile 32x64.
// ---------------------------------------------------------------------------
struct GemmArgs {
    const float* A[3];
    const float* W[3];
    const float* bias[3];
    float* C[3];
};

__global__ __launch_bounds__(256) void gemm_tf32_kernel(
    GemmArgs args, int M, int N, int K)
{
    const int z = blockIdx.z;
    const float* __restrict__ A    = args.A[z];
    const float* __restrict__ W    = args.W[z];
    const float* __restrict__ bias = args.bias[z];
    float* __restrict__ C          = args.C[z];

    // Af[mt(8)][ks(4)][lane(32)][slot(4)]  = 4096 floats, lane swizzled by ^ks
    // Bf[nt(16)][ks(4)][lane(32)][slot(2)] = 4096 floats, lane swizzled by ^nt
    __shared__ float Af[4096];
    __shared__ float Bf[4096];

    const int t = threadIdx.x;
    const int warp = t >> 5, lane = t & 31;
    const int g = lane >> 2, tig = lane & 3;
    const int wm = warp >> 1, wn = warp & 1;
    const int bm = blockIdx.y * 128;
    const int bn = blockIdx.x * 128;

    float acc[2][8][4];
#pragma unroll
    for (int i = 0; i < 2; i++)
#pragma unroll
        for (int j = 0; j < 8; j++)
#pragma unroll
            for (int l = 0; l < 4; l++) acc[i][j][l] = 0.f;

    float4 pa[4], pw[4];
    // prefetch k0 = 0
#pragma unroll
    for (int i = 0; i < 4; i++) {
        int f4 = t + i * 256;
        int ml = f4 >> 3, kl = (f4 & 7) * 4;
        pa[i] = *(const float4*)&A[(size_t)(bm + ml) * K + kl];
        int kl2 = f4 >> 5, nl = (f4 & 31) * 4;
        pw[i] = *(const float4*)&W[(size_t)kl2 * N + bn + nl];
    }

    for (int k0 = 0; k0 < K; k0 += 32) {
        __syncthreads();   // consumers of previous tile done
        // stage A from prefetch regs (lane ^= ks swizzle)
#pragma unroll
        for (int i = 0; i < 4; i++) {
            int f4 = t + i * 256;
            int ml = f4 >> 3, kl = (f4 & 7) * 4;
            int mt = ml >> 4, ga = ml & 7, sm = (ml >> 3) & 1;
            int ks = kl >> 3, sk = (kl >> 2) & 1;
            int slot = sm + 2 * sk;
            int blk = (mt * 4 + ks) * 32;
            float vv[4] = {pa[i].x, pa[i].y, pa[i].z, pa[i].w};
#pragma unroll
            for (int j = 0; j < 4; j++)
                Af[(blk + ((ga * 4 + j) ^ ks)) * 4 + slot] = to_tf32(vv[j]);
        }
        // stage W from prefetch regs (lane ^= nt swizzle)
#pragma unroll
        for (int i = 0; i < 4; i++) {
            int f4 = t + i * 256;
            int kl = f4 >> 5, nl = (f4 & 31) * 4;
            int ks = kl >> 3, tg = kl & 3, slot = (kl >> 2) & 1;
            float vv[4] = {pw[i].x, pw[i].y, pw[i].z, pw[i].w};
#pragma unroll
            for (int j = 0; j < 4; j++) {
                int n = nl + j;
                int nt = n >> 3, gb = n & 7;
                Bf[((nt * 4 + ks) * 32 + ((gb * 4 + tg) ^ nt)) * 2 + slot] = to_tf32(vv[j]);
            }
        }
        __syncthreads();

        // prefetch next tile (LDG overlaps the MMA mainloop below)
        if (k0 + 32 < K) {
            int kn = k0 + 32;
#pragma unroll
            for (int i = 0; i < 4; i++) {
                int f4 = t + i * 256;
                int ml = f4 >> 3, kl = (f4 & 7) * 4;
                pa[i] = *(const float4*)&A[(size_t)(bm + ml) * K + kn + kl];
                int kl2 = f4 >> 5, nl = (f4 & 31) * 4;
                pw[i] = *(const float4*)&W[(size_t)(kn + kl2) * N + bn + nl];
            }
        }

#pragma unroll
        for (int ks = 0; ks < 4; ks++) {
            float a[2][4];
#pragma unroll
            for (int lm = 0; lm < 2; lm++) {
                int mt = wm * 2 + lm;
                *(float4*)a[lm] = *(const float4*)&Af[((mt * 4 + ks) * 32 + (lane ^ ks)) * 4];
            }
#pragma unroll
            for (int ln = 0; ln < 8; ln++) {
                int nt = wn * 8 + ln;
                float b[2];
                *(float2*)b = *(const float2*)&Bf[((nt * 4 + ks) * 32 + (lane ^ nt)) * 2];
                mma_tf32(acc[0][ln], a[0], b);
                mma_tf32(acc[1][ln], a[1], b);
            }
        }
    }

    // epilogue: bias + store (STG.64)
#pragma unroll
    for (int lm = 0; lm < 2; lm++) {
        int m0 = bm + wm * 32 + lm * 16 + g;
#pragma unroll
        for (int ln = 0; ln < 8; ln++) {
            int n0 = bn + wn * 64 + ln * 8 + 2 * tig;
            float2 bi = *(const float2*)&bias[n0];
            float2 o0, o1;
            o0.x = acc[lm][ln][0] + bi.x;
            o0.y = acc[lm][ln][1] + bi.y;
            o1.x = acc[lm][ln][2] + bi.x;
            o1.y = acc[lm][ln][3] + bi.y;
            *(float2*)&C[(size_t)m0 * N + n0] = o0;
            *(float2*)&C[(size_t)(m0 + 8) * N + n0] = o1;
        }
    }
}

// ---------------------------------------------------------------------------
// RoPE in-place on Q and K; Q also gets the 1/sqrt(hd) score scale folded in.
// ---------------------------------------------------------------------------
__global__ void rope_kernel(float* __restrict__ Q, float* __restrict__ K)
{
    int idx = blockIdx.x * blockDim.x + threadIdx.x;
    const int TOTAL = B_ * T_ * NHEAD * 32;
    if (idx >= TOTAL) return;
    int i = idx & 31;
    int h = (idx >> 5) & (NHEAD - 1);
    int t = (idx >> 9) & (T_ - 1);
    int b = idx >> 20;

    float freq = (float)t / powf(10000.0f, (float)i / 32.0f);
    float s, c;
    sincosf(freq, &s, &c);

    int base = ((b * T_ + t) * D_MODEL) + h * HEAD_DIM;
    const float scale = 0.125f;  // 64^-0.5

    float ql = Q[base + i], qr = Q[base + i + 32];
    Q[base + i]      = (ql * c - qr * s) * scale;
    Q[base + i + 32] = (ql * s + qr * c) * scale;

    float kl = K[base + i], kr = K[base + i + 32];
    K[base + i]      = kl * c - kr * s;
    K[base + i + 32] = kl * s + kr * c;
}

// ---------------------------------------------------------------------------
// Flash attention, tf32 mma. 128-query tile / block, 256 threads = 8 warps.
// XOR-swizzled fragment staging (Q/K by ^ks, V by ^ntd) kills staging bank
// conflicts; K/V prefetched into registers while previous tile's MMAs run.
// Smem (floats):
//   Qf[mt(8)][ks(8)][lane][4]  = 8192  (A fragments, loaded once)
//   Kf[nt(8)][ks(8)][lane][2]  = 4096  (B fragments, per key tile)
//   Vf[nt(8)][kv(8)][lane][2]  = 4096  (B fragments, per key tile)
//   Ps: 8 warps x 16 x 68      = 8704  (P round-trip)
//   fk[64]
// ---------------------------------------------------------------------------
#define AT_SMEM_FLOATS (8192 + 4096 + 4096 + 8*16*68 + 64)
#define AT_SMEM_BYTES (AT_SMEM_FLOATS * 4)

__global__ __launch_bounds__(256) void attn_mma_kernel(
    const float* __restrict__ Q, const float* __restrict__ K,
    const float* __restrict__ V, float* __restrict__ O,
    const float* __restrict__ frac,
    const float* __restrict__ alpha_pos, const float* __restrict__ alpha_neg)
{
    extern __shared__ float sm[];
    float* Qf = sm;
    float* Kf = Qf + 8192;
    float* Vf = Kf + 4096;
    float* Ps = Vf + 4096;
    float* fk = Ps + 8 * 16 * 68;

    const int t = threadIdx.x;
    const int w = t >> 5, lane = t & 31;
    const int g = lane >> 2, tig = lane & 3;
    const int qt = blockIdx.x, h = blockIdx.y, b = blockIdx.z;
    const int t0 = qt * 128;
    const int bT = b * T_;

    const float ap = alpha_pos[h];
    const float an = alpha_neg[h];

    float* Pw = Ps + w * 16 * 68;

    // stage Q tile (128x64) into A-fragment layout (lane ^= ks)
#pragma unroll
    for (int i = 0; i < 8; i++) {
        int f4 = t + i * 256;               // 0..2047
        int ql = f4 >> 4, dl = (f4 & 15) * 4;
        float4 v = *(const float4*)&Q[(size_t)(bT + t0 + ql) * D_MODEL + h * HEAD_DIM + dl];
        int mt = ql >> 4, ga = ql & 7, smb = (ql >> 3) & 1;
        int ks = dl >> 3, sk = (dl >> 2) & 1;
        int slot = smb + 2 * sk;
        int blk = (mt * 8 + ks) * 32;
        float vv[4] = {v.x, v.y, v.z, v.w};
#pragma unroll
        for (int j = 0; j < 4; j++)
            Qf[(blk + ((ga * 4 + j) ^ ks)) * 4 + slot] = to_tf32(vv[j]);
    }

    const float fq_g  = frac[bT + t0 + w * 16 + g];
    const float fq_g8 = frac[bT + t0 + w * 16 + g + 8];

    float m_g = -1e30f, m_g8 = -1e30f, l_g = 0.f, l_g8 = 0.f;
    float oacc[8][4];
#pragma unroll
    for (int i = 0; i < 8; i++)
#pragma unroll
        for (int j = 0; j < 4; j++) oacc[i][j] = 0.f;

    // prefetch K/V tile 0
    float4 pk[4], pv[4];
#pragma unroll
    for (int i = 0; i < 4; i++) {
        int f4 = t + i * 256;               // 0..1023
        int kl = f4 >> 4, dl = (f4 & 15) * 4;
        size_t goff = (size_t)(bT + kl) * D_MODEL + h * HEAD_DIM + dl;
        pk[i] = *(const float4*)&K[goff];
        pv[i] = *(const float4*)&V[goff];
    }

    const int NT = T_ / 64;
    for (int kt = 0; kt < NT; kt++) {
        __syncthreads();   // prev tile's MMAs done (and Qf covered on iter 0)

        // stage K tile -> B fragments (lane ^= ks)
#pragma unroll
        for (int i = 0; i < 4; i++) {
            int f4 = t + i * 256;
            int kl = f4 >> 4, dl = (f4 & 15) * 4;
            int nt = kl >> 3, gb = kl & 7;
            int ks = dl >> 3, sk = (dl >> 2) & 1;
            int blk = (nt * 8 + ks) * 32;
            float vv[4] = {pk[i].x, pk[i].y, pk[i].z, pk[i].w};
#pragma unroll
            for (int j = 0; j < 4; j++)
                Kf[(blk + ((gb * 4 + j) ^ ks)) * 2 + sk] = to_tf32(vv[j]);
        }
        // stage V tile -> B fragments (lane ^= ntd)
#pragma unroll
        for (int i = 0; i < 4; i++) {
            int f4 = t + i * 256;
            int kl = f4 >> 4, dl = (f4 & 15) * 4;
            int kv = kl >> 3, tg = kl & 3, slot = (kl >> 2) & 1;
            int ntd = dl >> 3;
            int g0 = dl & 7;
            int blk = (ntd * 8 + kv) * 32;
            float vv[4] = {pv[i].x, pv[i].y, pv[i].z, pv[i].w};
#pragma unroll
            for (int j = 0; j < 4; j++)
                Vf[(blk + (((g0 + j) * 4 + tg) ^ ntd)) * 2 + slot] = to_tf32(vv[j]);
        }
        if (t < 64) fk[t] = frac[bT + kt * 64 + t];
        __syncthreads();

        // prefetch next K/V tile — LDG overlaps all MMA work below
        if (kt + 1 < NT) {
            int tk0n = (kt + 1) * 64;
#pragma unroll
            for (int i = 0; i < 4; i++) {
                int f4 = t + i * 256;
                int kl = f4 >> 4, dl = (f4 & 15) * 4;
                size_t goff = (size_t)(bT + tk0n + kl) * D_MODEL + h * HEAD_DIM + dl;
                pk[i] = *(const float4*)&K[goff];
                pv[i] = *(const float4*)&V[goff];
            }
        }

        // ---- S = Q @ K^T (16q x 64k per warp) ----
        float sacc[8][4];
#pragma unroll
        for (int i = 0; i < 8; i++)
#pragma unroll
            for (int j = 0; j < 4; j++) sacc[i][j] = 0.f;

#pragma unroll
        for (int ks = 0; ks < 8; ks++) {
            float a[4];
            *(float4*)a = *(const float4*)&Qf[((w * 8 + ks) * 32 + (lane ^ ks)) * 4];
#pragma unroll
            for (int nt = 0; nt < 8; nt++) {
                float bb[2];
                *(float2*)bb = *(const float2*)&Kf[((nt * 8 + ks) * 32 + (lane ^ ks)) * 2];
                mma_tf32(sacc[nt], a, bb);
            }
        }

        // ---- bias + online softmax (rows g, g+8; cols nt*8 + 2tig{,+1}) ----
        float tmax_g = -1e30f, tmax_g8 = -1e30f;
#pragma unroll
        for (int nt = 0; nt < 8; nt++) {
            float2 f2 = *(const float2*)&fk[nt * 8 + 2 * tig];
            float d0 = f2.x - fq_g;   sacc[nt][0] += (d0 > 0.f ? ap : an) * d0;
            float d1 = f2.y - fq_g;   sacc[nt][1] += (d1 > 0.f ? ap : an) * d1;
            float d2 = f2.x - fq_g8;  sacc[nt][2] += (d2 > 0.f ? ap : an) * d2;
            float d3 = f2.y - fq_g8;  sacc[nt][3] += (d3 > 0.f ? ap : an) * d3;
            tmax_g  = fmaxf(tmax_g,  fmaxf(sacc[nt][0], sacc[nt][1]));
            tmax_g8 = fmaxf(tmax_g8, fmaxf(sacc[nt][2], sacc[nt][3]));
        }
        tmax_g  = fmaxf(tmax_g,  __shfl_xor_sync(0xffffffffu, tmax_g, 1));
        tmax_g  = fmaxf(tmax_g,  __shfl_xor_sync(0xffffffffu, tmax_g, 2));
        tmax_g8 = fmaxf(tmax_g8, __shfl_xor_sync(0xffffffffu, tmax_g8, 1));
        tmax_g8 = fmaxf(tmax_g8, __shfl_xor_sync(0xffffffffu, tmax_g8, 2));

        float mn_g  = fmaxf(m_g,  tmax_g);
        float mn_g8 = fmaxf(m_g8, tmax_g8);
        float corr_g  = __expf(m_g  - mn_g);
        float corr_g8 = __expf(m_g8 - mn_g8);

        float rs_g = 0.f, rs_g8 = 0.f;
#pragma unroll
        for (int nt = 0; nt < 8; nt++) {
            float p0 = __expf(sacc[nt][0] - mn_g);
            float p1 = __expf(sacc[nt][1] - mn_g);
            float p2 = __expf(sacc[nt][2] - mn_g8);
            float p3 = __expf(sacc[nt][3] - mn_g8);
            rs_g  += p0 + p1;
            rs_g8 += p2 + p3;
            float2 st0; st0.x = to_tf32(p0); st0.y = to_tf32(p1);
            float2 st1; st1.x = to_tf32(p2); st1.y = to_tf32(p3);
            *(float2*)&Pw[g * 68 + nt * 8 + 2 * tig]       = st0;
            *(float2*)&Pw[(g + 8) * 68 + nt * 8 + 2 * tig] = st1;
        }
        rs_g  += __shfl_xor_sync(0xffffffffu, rs_g, 1);
        rs_g  += __shfl_xor_sync(0xffffffffu, rs_g, 2);
        rs_g8 += __shfl_xor_sync(0xffffffffu, rs_g8, 1);
        rs_g8 += __shfl_xor_sync(0xffffffffu, rs_g8, 2);

        l_g  = l_g  * corr_g  + rs_g;
        l_g8 = l_g8 * corr_g8 + rs_g8;
        m_g = mn_g; m_g8 = mn_g8;

#pragma unroll
        for (int nt = 0; nt < 8; nt++) {
            oacc[nt][0] *= corr_g;  oacc[nt][1] *= corr_g;
            oacc[nt][2] *= corr_g8; oacc[nt][3] *= corr_g8;
        }
        __syncwarp();

        // ---- O += P @ V ----
#pragma unroll
        for (int kv = 0; kv < 8; kv++) {
            float a[4];
            a[0] = Pw[g * 68 + kv * 8 + tig];
            a[1] = Pw[(g + 8) * 68 + kv * 8 + tig];
            a[2] = Pw[g * 68 + kv * 8 + tig + 4];
            a[3] = Pw[(g + 8) * 68 + kv * 8 + tig + 4];
#pragma unroll
            for (int nt = 0; nt < 8; nt++) {
                float bb[2];
                *(float2*)bb = *(const float2*)&Vf[((nt * 8 + kv) * 32 + (lane ^ nt)) * 2];
                mma_tf32(oacc[nt], a, bb);
            }
        }
    }

    // epilogue: normalize, store [B,T,D]
    float inv_g = 1.0f / l_g, inv_g8 = 1.0f / l_g8;
    int tq = t0 + w * 16 + g;
#pragma unroll
    for (int nt = 0; nt < 8; nt++) {
        int col = h * HEAD_DIM + nt * 8 + 2 * tig;
        float2 o0, o1;
        o0.x = oacc[nt][0] * inv_g;  o0.y = oacc[nt][1] * inv_g;
        o1.x = oacc[nt][2] * inv_g8; o1.y = oacc[nt][3] * inv_g8;
        *(float2*)&O[(size_t)(bT + tq) * D_MODEL + col] = o0;
        *(float2*)&O[(size_t)(bT + tq + 8) * D_MODEL + col] = o1;
    }
}

// ---------------------------------------------------------------------------
// Launch
// Inputs: 0 query, 1 key, 2 value, 3 frac, 4 Wq, 5 Wk, 6 Wv, 7 Wo,
//         8 bq, 9 bk, 10 bv, 11 bo, 12 alpha_pos, 13 alpha_neg
// ---------------------------------------------------------------------------
extern "C" void kernel_launch(void* const* d_in, const int* in_sizes, int n_in,
                              void* d_out, int out_size)
{
    const float* query = (const float*)d_in[0];
    const float* key   = (const float*)d_in[1];
    const float* value = (const float*)d_in[2];
    const float* frac  = (const float*)d_in[3];
    const float* Wq    = (const float*)d_in[4];
    const float* Wk    = (const float*)d_in[5];
    const float* Wv    = (const float*)d_in[6];
    const float* Wo    = (const float*)d_in[7];
    const float* bq    = (const float*)d_in[8];
    const float* bk    = (const float*)d_in[9];
    const float* bv    = (const float*)d_in[10];
    const float* bo    = (const float*)d_in[11];
    const float* a_pos = (const float*)d_in[12];
    const float* a_neg = (const float*)d_in[13];
    float* out = (float*)d_out;

    float *pQ, *pK, *pV, *pO;
    cudaGetSymbolAddress((void**)&pQ, g_Q);
    cudaGetSymbolAddress((void**)&pK, g_K);
    cudaGetSymbolAddress((void**)&pV, g_V);
    cudaGetSymbolAddress((void**)&pO, g_O);

    // fused QKV projections (z-indexed)
    GemmArgs qkv;
    qkv.A[0] = query; qkv.A[1] = key; qkv.A[2] = value;
    qkv.W[0] = Wq;    qkv.W[1] = Wk;  qkv.W[2] = Wv;
    qkv.bias[0] = bq; qkv.bias[1] = bk; qkv.bias[2] = bv;
    qkv.C[0] = pQ;    qkv.C[1] = pK;  qkv.C[2] = pV;

    dim3 qkv_grid(D_MODEL / 128, M_TOT / 128, 3);
    gemm_tf32_kernel<<<qkv_grid, 256>>>(qkv, M_TOT, D_MODEL, D_MODEL);

    int rope_threads = B_ * T_ * NHEAD * 32;
    rope_kernel<<<(rope_threads + 255) / 256, 256>>>(pQ, pK);

    cudaFuncSetAttribute(attn_mma_kernel, cudaFuncAttributeMaxDynamicSharedMemorySize, AT_SMEM_BYTES);
    attn_mma_kernel<<<dim3(T_ / 128, NHEAD, B_), 256, AT_SMEM_BYTES>>>(
        pQ, pK, pV, pO, frac, a_pos, a_neg);

    // output projection (single operand set, grid z = 1)
    GemmArgs og;
    og.A[0] = pO; og.A[1] = pO; og.A[2] = pO;
    og.W[0] = Wo; og.W[1] = Wo; og.W[2] = Wo;
    og.bias[0] = bo; og.bias[1] = bo; og.bias[2] = bo;
    og.C[0] = out; og.C[1] = out; og.C[2] = out;

    dim3 o_grid(D_MODEL / 128, M_TOT / 128, 1);
    gemm_tf32_kernel<<<o_grid, 256>>>(og, M_TOT, D_MODEL, D_MODEL);
}